// round 13
// baseline (speedup 1.0000x reference)
#include <cuda_runtime.h>
#include <cuda_fp16.h>

#define N_NODES  500000
#define N_EDGES  8000000
#define N_GRAPHS 4096
#define IN_DIM   9
#define HID      64
#define NTILES   31250   // N_NODES / 16 exactly

typedef unsigned long long u64;

// Scratch (static device globals — no allocation in kernel_launch)
__device__ __align__(128) uint4 g_xh [N_NODES * 2];  // fp16 features, 32B/row
__device__ __align__(128) uint4 g_agg[N_NODES * 2];  // fp16 agg, init = x
__device__ float g_acc[N_GRAPHS];
__device__ float g_v  [HID];              // v = w2 @ w3
__device__ float g_c;                     // c = b2 . w3
__device__ int   g_w64;                   // 1 if indices are int64
__device__ unsigned g_done;               // last-block counter for fused finish

// ---------------------------------------------------------------------------
// prep: zero accumulators; fold w2@w3 -> v, b2.w3 -> c; detect index dtype
// ---------------------------------------------------------------------------
__global__ void prep_kernel(const float* __restrict__ w2,
                            const float* __restrict__ b2,
                            const float* __restrict__ w3,
                            const int*   __restrict__ ei32)
{
    int t = blockIdx.x * blockDim.x + threadIdx.x;
    if (t < N_GRAPHS) g_acc[t] = 0.0f;
    if (t < HID) {
        float a = 0.0f;
        #pragma unroll
        for (int j = 0; j < HID; j++) a = fmaf(w2[t * HID + j], w3[j], a);
        g_v[t] = a;
    }
    if (t == 0) {
        float a = 0.0f;
        for (int j = 0; j < HID; j++) a = fmaf(b2[j], w3[j], a);
        g_c = a;
        g_done = 0u;
        int nz = 0;
        #pragma unroll
        for (int k = 0; k < 16; k++) nz |= ei32[2 * k + 1];
        g_w64 = (nz == 0) ? 1 : 0;
    }
}

// ---------------------------------------------------------------------------
// pad: convert x row (9 f32) -> 16 halves; write to g_xh and g_agg (init=x)
// ---------------------------------------------------------------------------
__global__ void __launch_bounds__(256, 8) pad_kernel(const float* __restrict__ x)
{
    int i = blockIdx.x * blockDim.x + threadIdx.x;
    if (i >= N_NODES) return;
    unsigned u[8];
    #pragma unroll
    for (int k = 0; k < 8; k++) u[k] = 0u;
    #pragma unroll
    for (int k = 0; k < IN_DIM; k++) {
        unsigned h = (unsigned)__half_as_ushort(__float2half_rn(x[i * IN_DIM + k]));
        u[k >> 1] |= h << ((k & 1) * 16);
    }
    uint4 lo = make_uint4(u[0], u[1], u[2], u[3]);
    uint4 hi = make_uint4(u[4], u[5], u[6], u[7]);
    g_xh [i * 2 + 0] = lo;  g_xh [i * 2 + 1] = hi;
    g_agg[i * 2 + 0] = lo;  g_agg[i * 2 + 1] = hi;
}

// ---------------------------------------------------------------------------
// edge scatter: agg[dst] += x[src]; two 128-bit vector REDs per edge
// (R5 sequential form — proven fastest)
// ---------------------------------------------------------------------------
__global__ void edge_kernel(const void* __restrict__ eiv)
{
    int t  = blockIdx.x * blockDim.x + threadIdx.x;
    int e0 = t * 4;
    if (e0 >= N_EDGES) return;

    int ss[4], dd[4];
    if (g_w64) {
        const long long* ei = (const long long*)eiv;
        longlong2 s01 = *reinterpret_cast<const longlong2*>(ei + e0);
        longlong2 s23 = *reinterpret_cast<const longlong2*>(ei + e0 + 2);
        longlong2 d01 = *reinterpret_cast<const longlong2*>(ei + N_EDGES + e0);
        longlong2 d23 = *reinterpret_cast<const longlong2*>(ei + N_EDGES + e0 + 2);
        ss[0] = (int)s01.x; ss[1] = (int)s01.y; ss[2] = (int)s23.x; ss[3] = (int)s23.y;
        dd[0] = (int)d01.x; dd[1] = (int)d01.y; dd[2] = (int)d23.x; dd[3] = (int)d23.y;
    } else {
        const int* ei = (const int*)eiv;
        int4 s = *reinterpret_cast<const int4*>(ei + e0);
        int4 d = *reinterpret_cast<const int4*>(ei + N_EDGES + e0);
        ss[0] = s.x; ss[1] = s.y; ss[2] = s.z; ss[3] = s.w;
        dd[0] = d.x; dd[1] = d.y; dd[2] = d.z; dd[3] = d.w;
    }

    #pragma unroll
    for (int k = 0; k < 4; k++) {
        const uint4* sp = &g_xh[(size_t)ss[k] * 2];
        uint4 a = __ldg(sp);
        uint4 b = __ldg(sp + 1);
        uint4* dp = &g_agg[(size_t)dd[k] * 2];
        asm volatile("red.global.add.noftz.v4.f16x2 [%0], {%1,%2,%3,%4};"
                     :: "l"(dp),     "r"(a.x), "r"(a.y), "r"(a.z), "r"(a.w) : "memory");
        asm volatile("red.global.add.noftz.v4.f16x2 [%0], {%1,%2,%3,%4};"
                     :: "l"(dp + 1), "r"(b.x), "r"(b.y), "r"(b.z), "r"(b.w) : "memory");
    }
}

// ---------------------------------------------------------------------------
// node MLP on tensor cores (mma.m16n8k16, fp16 in / fp32 acc)
//   Each warp: 16 nodes (one M-tile), K=16 (padded row), N=64 (8 n-tiles).
//   Bias in C init; relu + dot(v) epilogue in fp32; quad-reduce; atomicAdd.
// ---------------------------------------------------------------------------
__global__ void node_kernel(const float* __restrict__ w1,
                            const float* __restrict__ b1,
                            const void* __restrict__ batchv,
                            float* __restrict__ out,
                            const float* __restrict__ b3)
{
    __shared__ __align__(16) __half w1t[HID * 16];  // [n][k], 16 halves/row
    __shared__ __align__(8)  float  b1s[HID];
    __shared__ __align__(8)  float  vs [HID];
    __shared__ bool s_last;

    int tid = threadIdx.x;

    // stage weights: w1t[n][k] = fp16(w1[k][n]), k >= 9 -> 0
    for (int idx = tid; idx < HID * 16; idx += blockDim.x) {
        int n = idx >> 4, k = idx & 15;
        w1t[idx] = (k < IN_DIM) ? __float2half_rn(w1[k * HID + n]) : __ushort_as_half(0);
    }
    if (tid < HID) { b1s[tid] = b1[tid]; vs[tid] = g_v[tid]; }
    __syncthreads();

    int lane = tid & 31;
    int g    = lane >> 2;        // groupID  (0..7)
    int t    = lane & 3;         // threadID in group (0..3)
    int tile = blockIdx.x * 8 + (tid >> 5);

    if (tile < NTILES) {
        int base = tile * 16;

        // B fragments (constant per kernel): word t and t+4 of w1t row n
        const unsigned* w1w = reinterpret_cast<const unsigned*>(w1t);
        unsigned bf0[8], bf1[8];
        #pragma unroll
        for (int nt = 0; nt < 8; nt++) {
            int n = nt * 8 + g;
            bf0[nt] = w1w[n * 8 + t];
            bf1[nt] = w1w[n * 8 + t + 4];
        }

        // A fragments: words t, t+4 of agg rows base+g and base+g+8 (coalesced)
        const unsigned* aw = reinterpret_cast<const unsigned*>(g_agg);
        unsigned a0 = aw[(size_t)(base + g)     * 8 + t];
        unsigned a1 = aw[(size_t)(base + g + 8) * 8 + t];
        unsigned a2 = aw[(size_t)(base + g)     * 8 + t + 4];
        unsigned a3 = aw[(size_t)(base + g + 8) * 8 + t + 4];

        float sP0 = 0.0f, sP1 = 0.0f;   // partial s for rows g, g+8
        #pragma unroll
        for (int nt = 0; nt < 8; nt++) {
            int c0col = nt * 8 + 2 * t;
            float c0 = b1s[c0col], c1 = b1s[c0col + 1];
            float c2 = c0, c3 = c1;
            asm volatile(
                "mma.sync.aligned.m16n8k16.row.col.f32.f16.f16.f32 "
                "{%0,%1,%2,%3}, {%4,%5,%6,%7}, {%8,%9}, {%0,%1,%2,%3};"
                : "+f"(c0), "+f"(c1), "+f"(c2), "+f"(c3)
                : "r"(a0), "r"(a1), "r"(a2), "r"(a3), "r"(bf0[nt]), "r"(bf1[nt]));
            float2 vv = *reinterpret_cast<const float2*>(&vs[c0col]);
            sP0 = fmaf(fmaxf(c0, 0.0f), vv.x, fmaf(fmaxf(c1, 0.0f), vv.y, sP0));
            sP1 = fmaf(fmaxf(c2, 0.0f), vv.x, fmaf(fmaxf(c3, 0.0f), vv.y, sP1));
        }

        // reduce across the quad (lanes g*4 .. g*4+3)
        #pragma unroll
        for (int m = 1; m < 4; m <<= 1) {
            sP0 += __shfl_xor_sync(0xFFFFFFFFu, sP0, m);
            sP1 += __shfl_xor_sync(0xFFFFFFFFu, sP1, m);
        }

        if (t == 0) {
            int i0 = base + g, i1 = base + g + 8;
            int g0, g1;
            if (g_w64) {
                g0 = (int)((const long long*)batchv)[i0];
                g1 = (int)((const long long*)batchv)[i1];
            } else {
                g0 = ((const int*)batchv)[i0];
                g1 = ((const int*)batchv)[i1];
            }
            atomicAdd(&g_acc[g0], sP0 + g_c);
            atomicAdd(&g_acc[g1], sP1 + g_c);
        }
    }

    // fused finish: last block to retire writes the output
    __threadfence();
    __syncthreads();
    if (tid == 0) {
        unsigned prev = atomicAdd(&g_done, 1u);
        s_last = (prev == gridDim.x - 1);
    }
    __syncthreads();
    if (s_last) {
        float bias = b3[0];
        for (int q = tid; q < N_GRAPHS; q += blockDim.x) {
            float a;
            asm volatile("ld.global.acquire.gpu.b32 %0, [%1];"
                         : "=f"(a) : "l"(&g_acc[q]));
            out[q] = a + bias;
        }
    }
}

// ---------------------------------------------------------------------------
extern "C" void kernel_launch(void* const* d_in, const int* in_sizes, int n_in,
                              void* d_out, int out_size)
{
    const float* x     = (const float*)d_in[0];
    const void*  ei    = d_in[1];
    const void*  batch = d_in[2];
    const float* w1    = (const float*)d_in[3];
    const float* b1    = (const float*)d_in[4];
    const float* w2    = (const float*)d_in[5];
    const float* b2    = (const float*)d_in[6];
    const float* w3    = (const float*)d_in[7];
    const float* b3    = (const float*)d_in[8];
    float*       out   = (float*)d_out;

    prep_kernel<<<(N_GRAPHS + 255) / 256, 256>>>(w2, b2, w3, (const int*)ei);
    pad_kernel<<<(N_NODES + 255) / 256, 256>>>(x);
    edge_kernel<<<(N_EDGES / 4 + 255) / 256, 256>>>(ei);
    node_kernel<<<(NTILES + 7) / 8, 256>>>(w1, b1, batch, out, b3);
}

// round 14
// speedup vs baseline: 1.1099x; 1.1099x over previous
#include <cuda_runtime.h>
#include <cuda_fp16.h>

#define N_NODES  500000
#define N_EDGES  8000000
#define N_GRAPHS 4096
#define IN_DIM   9
#define HID      64
#define NTILES   31250   // N_NODES / 16 exactly
#define TPW      8       // tiles per warp in node_kernel

typedef unsigned long long u64;

// Scratch (static device globals — no allocation in kernel_launch)
__device__ __align__(128) uint4 g_xh [N_NODES * 2];  // fp16 features, 32B/row
__device__ __align__(128) uint4 g_agg[N_NODES * 2];  // fp16 agg, init = x
__device__ float g_acc[N_GRAPHS];
__device__ float g_v  [HID];              // v = w2 @ w3
__device__ float g_c;                     // c = b2 . w3
__device__ int   g_w64;                   // 1 if indices are int64
__device__ unsigned g_done;               // last-block counter for fused finish

// ---------------------------------------------------------------------------
// prep: zero accumulators; fold w2@w3 -> v, b2.w3 -> c; detect index dtype
// ---------------------------------------------------------------------------
__global__ void prep_kernel(const float* __restrict__ w2,
                            const float* __restrict__ b2,
                            const float* __restrict__ w3,
                            const int*   __restrict__ ei32)
{
    int t = blockIdx.x * blockDim.x + threadIdx.x;
    if (t < N_GRAPHS) g_acc[t] = 0.0f;
    if (t < HID) {
        float a = 0.0f;
        #pragma unroll
        for (int j = 0; j < HID; j++) a = fmaf(w2[t * HID + j], w3[j], a);
        g_v[t] = a;
    }
    if (t == 0) {
        float a = 0.0f;
        for (int j = 0; j < HID; j++) a = fmaf(b2[j], w3[j], a);
        g_c = a;
        g_done = 0u;
        int nz = 0;
        #pragma unroll
        for (int k = 0; k < 16; k++) nz |= ei32[2 * k + 1];
        g_w64 = (nz == 0) ? 1 : 0;
    }
}

// ---------------------------------------------------------------------------
// pad: convert x row (9 f32) -> 16 halves; write to g_xh and g_agg (init=x)
// ---------------------------------------------------------------------------
__global__ void __launch_bounds__(256, 8) pad_kernel(const float* __restrict__ x)
{
    int i = blockIdx.x * blockDim.x + threadIdx.x;
    if (i >= N_NODES) return;
    unsigned u[8];
    #pragma unroll
    for (int k = 0; k < 8; k++) u[k] = 0u;
    #pragma unroll
    for (int k = 0; k < IN_DIM; k++) {
        unsigned h = (unsigned)__half_as_ushort(__float2half_rn(x[i * IN_DIM + k]));
        u[k >> 1] |= h << ((k & 1) * 16);
    }
    uint4 lo = make_uint4(u[0], u[1], u[2], u[3]);
    uint4 hi = make_uint4(u[4], u[5], u[6], u[7]);
    g_xh [i * 2 + 0] = lo;  g_xh [i * 2 + 1] = hi;
    g_agg[i * 2 + 0] = lo;  g_agg[i * 2 + 1] = hi;
}

// ---------------------------------------------------------------------------
// edge scatter: agg[dst] += x[src]; two 128-bit vector REDs per edge
// (R5 sequential form — proven fastest)
// ---------------------------------------------------------------------------
__global__ void edge_kernel(const void* __restrict__ eiv)
{
    int t  = blockIdx.x * blockDim.x + threadIdx.x;
    int e0 = t * 4;
    if (e0 >= N_EDGES) return;

    int ss[4], dd[4];
    if (g_w64) {
        const long long* ei = (const long long*)eiv;
        longlong2 s01 = *reinterpret_cast<const longlong2*>(ei + e0);
        longlong2 s23 = *reinterpret_cast<const longlong2*>(ei + e0 + 2);
        longlong2 d01 = *reinterpret_cast<const longlong2*>(ei + N_EDGES + e0);
        longlong2 d23 = *reinterpret_cast<const longlong2*>(ei + N_EDGES + e0 + 2);
        ss[0] = (int)s01.x; ss[1] = (int)s01.y; ss[2] = (int)s23.x; ss[3] = (int)s23.y;
        dd[0] = (int)d01.x; dd[1] = (int)d01.y; dd[2] = (int)d23.x; dd[3] = (int)d23.y;
    } else {
        const int* ei = (const int*)eiv;
        int4 s = *reinterpret_cast<const int4*>(ei + e0);
        int4 d = *reinterpret_cast<const int4*>(ei + N_EDGES + e0);
        ss[0] = s.x; ss[1] = s.y; ss[2] = s.z; ss[3] = s.w;
        dd[0] = d.x; dd[1] = d.y; dd[2] = d.z; dd[3] = d.w;
    }

    #pragma unroll
    for (int k = 0; k < 4; k++) {
        const uint4* sp = &g_xh[(size_t)ss[k] * 2];
        uint4 a = __ldg(sp);
        uint4 b = __ldg(sp + 1);
        uint4* dp = &g_agg[(size_t)dd[k] * 2];
        asm volatile("red.global.add.noftz.v4.f16x2 [%0], {%1,%2,%3,%4};"
                     :: "l"(dp),     "r"(a.x), "r"(a.y), "r"(a.z), "r"(a.w) : "memory");
        asm volatile("red.global.add.noftz.v4.f16x2 [%0], {%1,%2,%3,%4};"
                     :: "l"(dp + 1), "r"(b.x), "r"(b.y), "r"(b.z), "r"(b.w) : "memory");
    }
}

// ---------------------------------------------------------------------------
// node MLP on tensor cores, TPW tiles per warp, all invariants in registers
// ---------------------------------------------------------------------------
__global__ void __launch_bounds__(256, 3)
node_kernel(const float* __restrict__ w1,
            const float* __restrict__ b1,
            const void* __restrict__ batchv,
            float* __restrict__ out,
            const float* __restrict__ b3)
{
    __shared__ __align__(16) __half w1t[HID * 16];  // [n][k], 16 halves/row
    __shared__ __align__(8)  float  b1s[HID];
    __shared__ __align__(8)  float  vs [HID];
    __shared__ bool s_last;

    int tid = threadIdx.x;

    // stage weights: w1t[n][k] = fp16(w1[k][n]), k >= 9 -> 0
    for (int idx = tid; idx < HID * 16; idx += blockDim.x) {
        int n = idx >> 4, k = idx & 15;
        w1t[idx] = (k < IN_DIM) ? __float2half_rn(w1[k * HID + n]) : __ushort_as_half(0);
    }
    if (tid < HID) { b1s[tid] = b1[tid]; vs[tid] = g_v[tid]; }
    __syncthreads();

    int lane = tid & 31;
    int g    = lane >> 2;        // groupID  (0..7)
    int t    = lane & 3;         // threadID in group (0..3)

    // hoisted loop invariants (per-thread registers)
    const unsigned* w1w = reinterpret_cast<const unsigned*>(w1t);
    unsigned bf0[8], bf1[8];
    float    bi0[8], bi1[8], vv0[8], vv1[8];
    #pragma unroll
    for (int nt = 0; nt < 8; nt++) {
        int n = nt * 8 + g;
        bf0[nt] = w1w[n * 8 + t];
        bf1[nt] = w1w[n * 8 + t + 4];
        int c0col = nt * 8 + 2 * t;
        bi0[nt] = b1s[c0col];  bi1[nt] = b1s[c0col + 1];
        vv0[nt] = vs [c0col];  vv1[nt] = vs [c0col + 1];
    }

    const unsigned* aw = reinterpret_cast<const unsigned*>(g_agg);
    int wtile0 = (blockIdx.x * 8 + (tid >> 5)) * TPW;

    #pragma unroll
    for (int tt = 0; tt < TPW; tt++) {
        int tile = wtile0 + tt;
        if (tile >= NTILES) break;
        int base = tile * 16;

        // A fragments: words t, t+4 of agg rows base+g and base+g+8
        unsigned a0 = aw[(size_t)(base + g)     * 8 + t];
        unsigned a1 = aw[(size_t)(base + g + 8) * 8 + t];
        unsigned a2 = aw[(size_t)(base + g)     * 8 + t + 4];
        unsigned a3 = aw[(size_t)(base + g + 8) * 8 + t + 4];

        float sP0 = 0.0f, sP1 = 0.0f;   // partial s for rows g, g+8
        #pragma unroll
        for (int nt = 0; nt < 8; nt++) {
            float c0 = bi0[nt], c1 = bi1[nt];
            float c2 = c0, c3 = c1;
            asm volatile(
                "mma.sync.aligned.m16n8k16.row.col.f32.f16.f16.f32 "
                "{%0,%1,%2,%3}, {%4,%5,%6,%7}, {%8,%9}, {%0,%1,%2,%3};"
                : "+f"(c0), "+f"(c1), "+f"(c2), "+f"(c3)
                : "r"(a0), "r"(a1), "r"(a2), "r"(a3), "r"(bf0[nt]), "r"(bf1[nt]));
            sP0 = fmaf(fmaxf(c0, 0.0f), vv0[nt], fmaf(fmaxf(c1, 0.0f), vv1[nt], sP0));
            sP1 = fmaf(fmaxf(c2, 0.0f), vv0[nt], fmaf(fmaxf(c3, 0.0f), vv1[nt], sP1));
        }

        // reduce across the quad (lanes g*4 .. g*4+3)
        #pragma unroll
        for (int m = 1; m < 4; m <<= 1) {
            sP0 += __shfl_xor_sync(0xFFFFFFFFu, sP0, m);
            sP1 += __shfl_xor_sync(0xFFFFFFFFu, sP1, m);
        }

        if (t == 0) {
            int i0 = base + g, i1 = base + g + 8;
            int g0, g1;
            if (g_w64) {
                g0 = (int)((const long long*)batchv)[i0];
                g1 = (int)((const long long*)batchv)[i1];
            } else {
                g0 = ((const int*)batchv)[i0];
                g1 = ((const int*)batchv)[i1];
            }
            atomicAdd(&g_acc[g0], sP0 + g_c);
            atomicAdd(&g_acc[g1], sP1 + g_c);
        }
    }

    // fused finish: last block to retire writes the output
    __threadfence();
    __syncthreads();
    if (tid == 0) {
        unsigned prev = atomicAdd(&g_done, 1u);
        s_last = (prev == gridDim.x - 1);
    }
    __syncthreads();
    if (s_last) {
        float bias = b3[0];
        for (int q = tid; q < N_GRAPHS; q += blockDim.x) {
            float a;
            asm volatile("ld.global.acquire.gpu.b32 %0, [%1];"
                         : "=f"(a) : "l"(&g_acc[q]));
            out[q] = a + bias;
        }
    }
}

// ---------------------------------------------------------------------------
extern "C" void kernel_launch(void* const* d_in, const int* in_sizes, int n_in,
                              void* d_out, int out_size)
{
    const float* x     = (const float*)d_in[0];
    const void*  ei    = d_in[1];
    const void*  batch = d_in[2];
    const float* w1    = (const float*)d_in[3];
    const float* b1    = (const float*)d_in[4];
    const float* w2    = (const float*)d_in[5];
    const float* b2    = (const float*)d_in[6];
    const float* w3    = (const float*)d_in[7];
    const float* b3    = (const float*)d_in[8];
    float*       out   = (float*)d_out;

    prep_kernel<<<(N_GRAPHS + 255) / 256, 256>>>(w2, b2, w3, (const int*)ei);
    pad_kernel<<<(N_NODES + 255) / 256, 256>>>(x);
    edge_kernel<<<(N_EDGES / 4 + 255) / 256, 256>>>(ei);
    int tiles_per_block = 8 * TPW;
    node_kernel<<<(NTILES + tiles_per_block - 1) / tiles_per_block, 256>>>(w1, b1, batch, out, b3);
}